// round 17
// baseline (speedup 1.0000x reference)
#include <cuda_runtime.h>
#include <cuda_fp16.h>
#include <math.h>
#include <stdint.h>

// Problem constants (fixed): B=4, S=2048, D=1024, H=16, dk=64
#define BB   4
#define SS   2048
#define DD   1024
#define HH   16
#define DKK  64
#define BHN  (BB*HH)        // 64
#define MM   (BB*SS)        // 8192

// ---------------- scratch (device globals; no allocation allowed) -----------
__device__ __half g_xh[(size_t)MM * DD];          // X in fp16
__device__ __half g_wh[(size_t)3 * DD * DD];      // Wq|Wk|Wv fp16
__device__ __half g_woh[(size_t)DD * DD];         // Wo fp16
__device__ __half g_qh[(size_t)BHN * SS * DKK];   // Q*log2e/8, [B,H,S,dk]
__device__ __half g_kh[(size_t)BHN * SS * DKK];   // K [B,H,S,dk]
__device__ __half g_vh[(size_t)BHN * DKK * SS];   // V TRANSPOSED [B,H,dk,S]
__device__ __half g_atth[(size_t)MM * DD];        // attn out [B,S,D]

// ======================= helpers ===========================================
__device__ __forceinline__ uint32_t pack_h2(float lo, float hi) {
    uint32_t u;
    asm("cvt.rn.f16x2.f32 %0, %1, %2;" : "=r"(u) : "f"(hi), "f"(lo));
    return u;
}
__device__ __forceinline__ uint32_t ex2_h2(uint32_t s2) {  // 2^x on fp16 pair
    uint32_t r;
    asm("ex2.approx.f16x2 %0, %1;" : "=r"(r) : "r"(s2));
    return r;
}
__device__ __forceinline__ void mma_f16(float c[4], uint4 a, uint2 b) {
    asm volatile(
        "mma.sync.aligned.m16n8k16.row.col.f32.f16.f16.f32 "
        "{%0,%1,%2,%3}, {%4,%5,%6,%7}, {%8,%9}, {%0,%1,%2,%3};"
        : "+f"(c[0]), "+f"(c[1]), "+f"(c[2]), "+f"(c[3])
        : "r"(a.x), "r"(a.y), "r"(a.z), "r"(a.w), "r"(b.x), "r"(b.y));
}
__device__ __forceinline__ uint32_t smem_u32(const void* p) {
    uint32_t a;
    asm("{ .reg .u64 t; cvta.to.shared.u64 t, %1; cvt.u32.u64 %0, t; }"
        : "=r"(a) : "l"(p));
    return a;
}
__device__ __forceinline__ void ldmx4(uint32_t& d0, uint32_t& d1,
                                      uint32_t& d2, uint32_t& d3, uint32_t addr) {
    asm volatile("ldmatrix.sync.aligned.m8n8.x4.shared.b16 {%0,%1,%2,%3}, [%4];"
                 : "=r"(d0), "=r"(d1), "=r"(d2), "=r"(d3) : "r"(addr));
}
__device__ __forceinline__ void cpasync16(uint32_t dst, const void* src) {
    asm volatile("cp.async.cg.shared.global [%0], [%1], 16;" :: "r"(dst), "l"(src));
}
#define CP_COMMIT() asm volatile("cp.async.commit_group;" ::: "memory")
#define CP_WAIT2()  asm volatile("cp.async.wait_group 2;" ::: "memory")
#define CP_WAIT1()  asm volatile("cp.async.wait_group 1;" ::: "memory")
#define CP_WAIT0()  asm volatile("cp.async.wait_group 0;" ::: "memory")

// ============================================================================
// Converters fp32 -> fp16
// ============================================================================
__global__ __launch_bounds__(256) void conv_h(
    const float* __restrict__ in, __half* __restrict__ out, int n4)
{
    int i = blockIdx.x * blockDim.x + threadIdx.x;
    if (i < n4) {
        float4 v = ((const float4*)in)[i];
        uint2 u;
        u.x = pack_h2(v.x, v.y);
        u.y = pack_h2(v.z, v.w);
        ((uint2*)out)[i] = u;
    }
}

__global__ __launch_bounds__(256) void conv_w4(
    const float* __restrict__ w0, const float* __restrict__ w1,
    const float* __restrict__ w2, const float* __restrict__ w3)
{
    const int n4w = DD * DD / 4;
    const int per = n4w / 256;
    const int z   = blockIdx.x / per;
    const int i   = (blockIdx.x % per) * 256 + threadIdx.x;
    const float* in = (z == 0) ? w0 : (z == 1) ? w1 : (z == 2) ? w2 : w3;
    __half* out = (z < 3) ? (g_wh + (size_t)z * DD * DD) : g_woh;
    float4 v = ((const float4*)in)[i];
    uint2 u;
    u.x = pack_h2(v.x, v.y);
    u.y = pack_h2(v.z, v.w);
    ((uint2*)out)[i] = u;
}

// ============================================================================
// fp16 tensor-core GEMM v2 (verified R15):  C[m,n] = sum_k A[m,k] * W[n,k]
// ============================================================================
#define MH_A_B      (128 * 64)               // 8192
#define MH_B_B      (256 * 64)               // 16384
#define MH_STAGE_B  (MH_A_B + MH_B_B)        // 24576
#define MH_STAGES   3
#define MH_SMEM_B   (MH_STAGES * MH_STAGE_B) // 73728
#define MH_KT       (DD / 32)                // 32 chunks
#define QSCALE      0.18033688011112042f     // log2(e)/8

template <bool SCATTER>
__global__ __launch_bounds__(256) void mm_h(
    const __half* __restrict__ Ag,
    const __half* __restrict__ Wbase,
    float* __restrict__ Out0)
{
    extern __shared__ char smc[];
    const uint32_t sbase = smem_u32(smc);

    const __half* W;
    __half* OutH = nullptr;
    int z = 0;
    if (SCATTER) {
        z = blockIdx.z;
        W = Wbase + (size_t)z * DD * DD;
        OutH = (z == 0) ? g_qh : (z == 1) ? g_kh : g_vh;
    } else {
        W = Wbase;
    }

    const int t  = threadIdx.x;
    const int m0 = blockIdx.y * 128;
    const int n0 = blockIdx.x * 256;

    const int arow_i = t >> 1;
    const int apair  = t & 1;
    const __half* arow = Ag + (size_t)(m0 + arow_i) * DD;
    const __half* brow = W  + (size_t)(n0 + t) * DD;
    uint32_t a_off[2], b_off[4];
#pragma unroll
    for (int j = 0; j < 2; j++) {
        const int g = apair * 2 + j;
        a_off[j] = (uint32_t)arow_i * 64 + ((g ^ ((arow_i >> 1) & 3)) * 16);
    }
#pragma unroll
    for (int g = 0; g < 4; g++)
        b_off[g] = (uint32_t)t * 64 + ((g ^ ((t >> 1) & 3)) * 16);

    const int lane = t & 31, wid = t >> 5;
    const int wm = wid >> 2, wn = wid & 3;
    const int a_r15 = lane & 15;
    const int a_kb  = lane >> 4;
    const int a_sw  = (a_r15 >> 1) & 3;
    const int nb    = (lane >> 4) * 8 + (lane & 7);
    const int b_kb  = (lane >> 3) & 1;
    const int b_sw  = (nb >> 1) & 3;

    float acc[4][8][4];
#pragma unroll
    for (int mi = 0; mi < 4; mi++)
#pragma unroll
        for (int ni = 0; ni < 8; ni++)
#pragma unroll
            for (int c = 0; c < 4; c++) acc[mi][ni][c] = 0.f;

#pragma unroll
    for (int s = 0; s < MH_STAGES; s++) {
        const uint32_t ab = sbase + s * MH_STAGE_B;
        const uint32_t bbs = ab + MH_A_B;
        const __half* as = arow + s * 32;
        const __half* bs = brow + s * 32;
#pragma unroll
        for (int j = 0; j < 2; j++)
            cpasync16(ab + a_off[j], as + (apair * 2 + j) * 8);
#pragma unroll
        for (int g = 0; g < 4; g++)
            cpasync16(bbs + b_off[g], bs + g * 8);
        CP_COMMIT();
    }

    int buf = 0;
    for (int kt = 0; kt < MH_KT; kt++) {
        CP_WAIT2();
        __syncthreads();

        const uint32_t Ab = sbase + buf * MH_STAGE_B;
        const uint32_t Bb = Ab + MH_A_B;
#pragma unroll
        for (int ks = 0; ks < 2; ks++) {
            uint4 af[4];
#pragma unroll
            for (int mi = 0; mi < 4; mi++) {
                const int row = wm * 64 + mi * 16 + a_r15;
                ldmx4(af[mi].x, af[mi].y, af[mi].z, af[mi].w,
                      Ab + row * 64 + (((ks * 2 + a_kb) ^ a_sw) * 16));
            }
            uint2 bf[8];
#pragma unroll
            for (int ng = 0; ng < 4; ng++) {
                uint32_t d0, d1, d2, d3;
                const int row = wn * 64 + ng * 16 + nb;
                ldmx4(d0, d1, d2, d3,
                      Bb + row * 64 + (((ks * 2 + b_kb) ^ b_sw) * 16));
                bf[2 * ng]     = make_uint2(d0, d1);
                bf[2 * ng + 1] = make_uint2(d2, d3);
            }
#pragma unroll
            for (int mi = 0; mi < 4; mi++)
#pragma unroll
                for (int ni = 0; ni < 8; ni++)
                    mma_f16(acc[mi][ni], af[mi], bf[ni]);
        }
        __syncthreads();

        if (kt + 3 < MH_KT) {
            const uint32_t ab = sbase + buf * MH_STAGE_B;
            const uint32_t bbs = ab + MH_A_B;
            const __half* as = arow + (kt + 3) * 32;
            const __half* bs = brow + (kt + 3) * 32;
#pragma unroll
            for (int j = 0; j < 2; j++)
                cpasync16(ab + a_off[j], as + (apair * 2 + j) * 8);
#pragma unroll
            for (int g = 0; g < 4; g++)
                cpasync16(bbs + b_off[g], bs + g * 8);
        }
        CP_COMMIT();
        if (++buf == MH_STAGES) buf = 0;
    }

    const int r = lane >> 2, q = lane & 3;
#pragma unroll
    for (int mi = 0; mi < 4; mi++) {
        const int rowm = m0 + wm * 64 + mi * 16 + r;
#pragma unroll
        for (int ni = 0; ni < 8; ni++) {
            const int coln = n0 + wn * 64 + ni * 8 + 2 * q;
            float c0 = acc[mi][ni][0], c1 = acc[mi][ni][1];
            float c2 = acc[mi][ni][2], c3 = acc[mi][ni][3];
            if (SCATTER) {
                if (z == 0) { c0 *= QSCALE; c1 *= QSCALE; c2 *= QSCALE; c3 *= QSCALE; }
                const int b  = rowm >> 11;
                const int s0 = rowm & 2047;
                const int h  = coln >> 6, kc = coln & 63;
                if (z == 2) {
                    __half* base = OutH + ((size_t)(b * HH + h) * DKK) * SS;
                    base[(size_t)kc * SS + s0]           = __float2half_rn(c0);
                    base[(size_t)(kc + 1) * SS + s0]     = __float2half_rn(c1);
                    base[(size_t)kc * SS + s0 + 8]       = __float2half_rn(c2);
                    base[(size_t)(kc + 1) * SS + s0 + 8] = __float2half_rn(c3);
                } else {
                    uint32_t* base = (uint32_t*)(OutH +
                        ((size_t)(b * HH + h) * SS) * DKK) + (kc >> 1);
                    base[(size_t)s0 * 32]       = pack_h2(c0, c1);
                    base[(size_t)(s0 + 8) * 32] = pack_h2(c2, c3);
                }
            } else {
                *(float2*)&Out0[(size_t)rowm * DD + coln]       = make_float2(c0, c1);
                *(float2*)&Out0[(size_t)(rowm + 8) * DD + coln] = make_float2(c2, c3);
            }
        }
    }
}

// ============================================================================
// fp16 tensor-core causal attention v3: unnormalized exp2 softmax with
//   half2 EX2 (halves MUFU demand, the measured bottleneck), per-warp skip
//   of fully-masked key tiles. 256 threads = 8 warps, Q tile 128 rows.
// ============================================================================
#define AH_TILE_B   8192                      // 64 rows x 128B
#define AH_STAGE_B  (2 * AH_TILE_B)           // K + V = 16384
#define AH_P_OFF    (2 * AH_STAGE_B)          // 32768
#define AH_SMEM_B   (AH_P_OFF + 8 * 2048)     // 49152

__global__ __launch_bounds__(256) void attn_h()
{
    extern __shared__ char smc[];
    const uint32_t sb = smem_u32(smc);
    uint32_t* su = (uint32_t*)smc;

    const int qt  = blockIdx.x;               // 128-row Q tile (16 tiles)
    const int bh  = blockIdx.y;
    const int tid = threadIdx.x;
    const int w   = tid >> 5;
    const int lane = tid & 31;
    const int r = lane >> 2, q = lane & 3;
    const int q0 = qt * 128;

    const uint32_t* Qp32 = (const uint32_t*)(g_qh + (size_t)bh * SS * DKK);
    const __half* Kp = g_kh + (size_t)bh * SS * DKK;
    const __half* Vt = g_vh + (size_t)bh * DKK * SS;   // [dk][S]

    uint32_t* Pw32 = su + (AH_P_OFF >> 2) + w * 512;   // 16 x 128B per warp
    const uint32_t PwA = sb + AH_P_OFF + w * 2048;

    const int lrow = tid >> 2;
    const int lg0  = (tid & 3) * 2;

    const int nb   = (lane >> 4) * 8 + (lane & 7);
    const int b_kb = (lane >> 3) & 1;
    const int b_sw = lane & 7;
    const int a_r  = lane & 15;
    const int a_kb = lane >> 4;
    const int a_sw = lane & 7;

    const int row0 = q0 + w * 16 + r;
    uint4 qf[4];
#pragma unroll
    for (int ks = 0; ks < 4; ks++) {
        qf[ks].x = Qp32[(size_t)row0 * 32 + ks * 8 + q];
        qf[ks].y = Qp32[(size_t)(row0 + 8) * 32 + ks * 8 + q];
        qf[ks].z = Qp32[(size_t)row0 * 32 + ks * 8 + q + 4];
        qf[ks].w = Qp32[(size_t)(row0 + 8) * 32 + ks * 8 + q + 4];
    }

    float o[8][4];
#pragma unroll
    for (int nf = 0; nf < 8; nf++)
#pragma unroll
        for (int c = 0; c < 4; c++) o[nf][c] = 0.f;
    float ol[4] = {0.f, 0.f, 0.f, 0.f};
    const uint2 bones = make_uint2(0x3C003C00u, 0x3C003C00u);  // fp16 1.0 x4

    const int nkt = 2 * qt + 2;   // key tiles covering rows q0..q0+127
    const int wlast = q0 + w * 16 + 15;   // last row this warp owns

    // prologue: tile 0 into stage 0
    {
        const uint32_t Kd = sb, Vd = sb + AH_TILE_B;
#pragma unroll
        for (int j = 0; j < 2; j++) {
            const int g = lg0 + j;
            const uint32_t soff = lrow * 128 + ((g ^ (lrow & 7)) * 16);
            cpasync16(Kd + soff, Kp + (size_t)lrow * DKK + g * 8);
            cpasync16(Vd + soff, Vt + (size_t)lrow * SS + g * 8);
        }
        CP_COMMIT();
    }

    for (int kt = 0; kt < nkt; kt++) {
        if (kt + 1 < nkt) {
            const uint32_t st = sb + ((kt + 1) & 1) * AH_STAGE_B;
            const uint32_t Kd = st, Vd = st + AH_TILE_B;
            const int kn = (kt + 1) * 64;
#pragma unroll
            for (int j = 0; j < 2; j++) {
                const int g = lg0 + j;
                const uint32_t soff = lrow * 128 + ((g ^ (lrow & 7)) * 16);
                cpasync16(Kd + soff, Kp + (size_t)(kn + lrow) * DKK + g * 8);
                cpasync16(Vd + soff, Vt + (size_t)lrow * SS + kn + g * 8);
            }
            CP_COMMIT();
            CP_WAIT1();
        } else {
            CP_WAIT0();
        }
        __syncthreads();

        // skip key tiles entirely in this warp's causal future
        if (kt * 64 <= wlast) {
            const uint32_t Kb = sb + (kt & 1) * AH_STAGE_B;
            const uint32_t Vb = Kb + AH_TILE_B;

            // ---- S = Q' * K^T ----
            float s[8][4];
#pragma unroll
            for (int nf = 0; nf < 8; nf++)
#pragma unroll
                for (int c = 0; c < 4; c++) s[nf][c] = 0.f;
#pragma unroll
            for (int ks = 0; ks < 4; ks++) {
                uint2 bf[8];
#pragma unroll
                for (int ng = 0; ng < 4; ng++) {
                    uint32_t d0, d1, d2, d3;
                    const int row = ng * 16 + nb;
                    ldmx4(d0, d1, d2, d3,
                          Kb + row * 128 + (((ks * 2 + b_kb) ^ b_sw) * 16));
                    bf[2 * ng]     = make_uint2(d0, d1);
                    bf[2 * ng + 1] = make_uint2(d2, d3);
                }
                const uint4 a = qf[ks];
#pragma unroll
                for (int nf = 0; nf < 8; nf++) mma_f16(s[nf], a, bf[nf]);
            }

            // ---- causal mask (warp-uniform gate; elementwise key>row test) ----
            if (kt * 64 + 63 > q0 + w * 16) {
#pragma unroll
                for (int nf = 0; nf < 8; nf++) {
                    const int c0 = kt * 64 + nf * 8 + 2 * q;
                    if (c0     > row0)     s[nf][0] = -INFINITY;
                    if (c0 + 1 > row0)     s[nf][1] = -INFINITY;
                    if (c0     > row0 + 8) s[nf][2] = -INFINITY;
                    if (c0 + 1 > row0 + 8) s[nf][3] = -INFINITY;
                }
            }

            // ---- P = 2^s, half2 EX2 (packed fp16 directly) ----
#pragma unroll
            for (int nf = 0; nf < 8; nf++) {
                const uint32_t p01 = ex2_h2(pack_h2(s[nf][0], s[nf][1]));
                const uint32_t p23 = ex2_h2(pack_h2(s[nf][2], s[nf][3]));
                const int gsw0 = (nf ^ (r & 7)) * 4 + q;
                const int gsw1 = (nf ^ ((r + 8) & 7)) * 4 + q;
                Pw32[r * 32 + gsw0]       = p01;
                Pw32[(r + 8) * 32 + gsw1] = p23;
            }
            __syncwarp();

            // ---- O += P * V ; l += P * 1 (ones-MMA) ----
#pragma unroll
            for (int ks = 0; ks < 4; ks++) {
                uint4 ap;
                ldmx4(ap.x, ap.y, ap.z, ap.w,
                      PwA + a_r * 128 + (((ks * 2 + a_kb) ^ a_sw) * 16));
                uint2 bf[8];
#pragma unroll
                for (int ng = 0; ng < 4; ng++) {
                    uint32_t d0, d1, d2, d3;
                    const int row = ng * 16 + nb;
                    ldmx4(d0, d1, d2, d3,
                          Vb + row * 128 + (((ks * 2 + b_kb) ^ b_sw) * 16));
                    bf[2 * ng]     = make_uint2(d0, d1);
                    bf[2 * ng + 1] = make_uint2(d2, d3);
                }
#pragma unroll
                for (int nf = 0; nf < 8; nf++) mma_f16(o[nf], ap, bf[nf]);
                mma_f16(ol, ap, bones);
            }
        }
        __syncthreads();
    }

    // ---- epilogue: O / l -> g_atth (fp16, concatenated [B,S,D]) ----
    const int bb = bh >> 4, hh = bh & 15;
    const float inv0 = 1.f / ol[0], inv1 = 1.f / ol[2];
    uint32_t* Ob32 = (uint32_t*)g_atth;
    const size_t mrow = (size_t)bb * SS + row0;
#pragma unroll
    for (int nf = 0; nf < 8; nf++) {
        Ob32[mrow * 512 + hh * 32 + nf * 4 + q] =
            pack_h2(o[nf][0] * inv0, o[nf][1] * inv0);
        Ob32[(mrow + 8) * 512 + hh * 32 + nf * 4 + q] =
            pack_h2(o[nf][2] * inv1, o[nf][3] * inv1);
    }
}

// ============================================================================
extern "C" void kernel_launch(void* const* d_in, const int* in_sizes, int n_in,
                              void* d_out, int out_size)
{
    (void)in_sizes; (void)n_in; (void)out_size;
    const float* x  = (const float*)d_in[0];
    const float* Wq = (const float*)d_in[1];
    const float* Wk = (const float*)d_in[2];
    const float* Wv = (const float*)d_in[3];
    const float* Wo = (const float*)d_in[4];
    float* out = (float*)d_out;

    cudaFuncSetAttribute(mm_h<true>,
                         cudaFuncAttributeMaxDynamicSharedMemorySize, MH_SMEM_B);
    cudaFuncSetAttribute(mm_h<false>,
                         cudaFuncAttributeMaxDynamicSharedMemorySize, MH_SMEM_B);
    cudaFuncSetAttribute(attn_h,
                         cudaFuncAttributeMaxDynamicSharedMemorySize, AH_SMEM_B);

    __half *xh_p, *wh_p, *woh_p, *atth_p;
    cudaGetSymbolAddress((void**)&xh_p, g_xh);
    cudaGetSymbolAddress((void**)&wh_p, g_wh);
    cudaGetSymbolAddress((void**)&woh_p, g_woh);
    cudaGetSymbolAddress((void**)&atth_p, g_atth);

    const int n4x = MM * DD / 4;
    const int n4w = DD * DD / 4;
    conv_h<<<n4x / 256, 256>>>(x, xh_p, n4x);
    conv_w4<<<4 * (n4w / 256), 256>>>(Wq, Wk, Wv, Wo);

    // QKV projections (fp16 MMA; Q pre-scaled; V transposed)
    mm_h<true><<<dim3(DD / 256, MM / 128, 3), 256, MH_SMEM_B>>>(
        xh_p, wh_p, nullptr);
    // causal attention (fp16 MMA, unnormalized half2 exp2, ones-MMA row sums)
    attn_h<<<dim3(SS / 128, BHN), 256, AH_SMEM_B>>>();
    // output projection (fp16 MMA, fp32 out)
    mm_h<false><<<dim3(DD / 256, MM / 128), 256, MH_SMEM_B>>>(
        atth_p, woh_p, out);
}